// round 8
// baseline (speedup 1.0000x reference)
#include <cuda_runtime.h>
#include <cuda_bf16.h>
#include <cstdint>
#include <cstddef>

#define B_ 8
#define N_ 8192
#define D_ 256

typedef unsigned long long ull;
typedef unsigned int u32;

// tcgen05 is arch-specific (sm_103a). The harness also builds a baseline
// compute_103 stage where tcgen05 is illegal -> gate + FFMA fallback.
#if !defined(__CUDA_ARCH__) || defined(__CUDA_ARCH_FEAT_SM103_ALL) || defined(__CUDA_ARCH_FEAT_SM100_ALL) || defined(__CUDA_ARCH_FEAT_SM101_ALL)
#define TCOK 1
#else
#define TCOK 0
#endif

// ---------------- device scratch ----------------
__device__ __nv_bfloat16 g_MTH[B_ * D_ * D_];   // (Wq^T aw)^T hi [b][e][i]
__device__ __nv_bfloat16 g_MTL[B_ * D_ * D_];
__device__ float g_S[B_ * D_ * D_];
__device__ float g_T1[B_ * D_ * D_];
__device__ float g_A[B_ * D_ * D_];
__device__ float g_rk[B_ * D_];
__device__ float g_rv[B_ * D_];
__device__ float g_u[B_ * D_];
__device__ float g_w[B_ * D_];
__device__ float g_t[B_ * D_];
__device__ float g_cm[B_];
__device__ int   g_kind;     // 1 = byte-packed bool mask, 0 = 4-byte mask
__device__ float g_m[B_ * N_];

// ---------------- f32x2 helpers ----------------
__device__ __forceinline__ ull pack2(float lo, float hi) {
    ull r; asm("mov.b64 %0, {%1,%2};" : "=l"(r) : "f"(lo), "f"(hi)); return r;
}
__device__ __forceinline__ void unpack2(ull v, float& lo, float& hi) {
    asm("mov.b64 {%0,%1}, %2;" : "=f"(lo), "=f"(hi) : "l"(v));
}
__device__ __forceinline__ ull ffma2(ull a, ull b, ull c) {
    ull d; asm("fma.rn.f32x2 %0, %1, %2, %3;" : "=l"(d) : "l"(a), "l"(b), "l"(c)); return d;
}

// split f32 pair -> bf16x2 hi + bf16x2 lo (elem0 in low half)
__device__ __forceinline__ void cvt2(float x0, float x1, u32& h2, u32& l2) {
    asm("cvt.rn.bf16x2.f32 %0, %1, %2;" : "=r"(h2) : "f"(x1), "f"(x0));
    float hf0 = __uint_as_float(h2 << 16);
    float hf1 = __uint_as_float(h2 & 0xFFFF0000u);
    float d0 = x0 - hf0, d1 = x1 - hf1;
    asm("cvt.rn.bf16x2.f32 %0, %1, %2;" : "=r"(l2) : "f"(d1), "f"(d0));
}

// ---------------- tcgen05 helpers (guarded) ----------------
#if TCOK
__device__ __forceinline__ u32 smem_u32(const void* p) {
    u32 a; asm("{ .reg .u64 t; cvta.to.shared.u64 t, %1; cvt.u32.u64 %0, t; }" : "=r"(a) : "l"(p));
    return a;
}
__device__ __forceinline__ int elect1() {
    u32 p;
    asm volatile("{\n\t.reg .pred p;\n\telect.sync _|p, 0xFFFFFFFF;\n\tselp.b32 %0, 1, 0, p;\n\t}" : "=r"(p));
    return (int)p;
}
__device__ __forceinline__ void mbar_init(u32 mbar, u32 cnt) {
    asm volatile("mbarrier.init.shared.b64 [%0], %1;" :: "r"(mbar), "r"(cnt) : "memory");
}
__device__ __forceinline__ void mbar_inval(u32 mbar) {
    asm volatile("mbarrier.inval.shared.b64 [%0];" :: "r"(mbar) : "memory");
}
__device__ __forceinline__ void mbar_wait(u32 mbar, u32 parity) {
    asm volatile(
        "{\n\t.reg .pred P;\n\t"
        "WL_%=:\n\t"
        "mbarrier.try_wait.parity.acquire.cta.shared::cta.b64 P, [%0], %1, 0x989680;\n\t"
        "@P bra WD_%=;\n\t"
        "bra.uni WL_%=;\n\t"
        "WD_%=:\n\t}"
        :: "r"(mbar), "r"(parity) : "memory");
}
__device__ __forceinline__ void tmem_alloc(u32 smem_dst, u32 ncols) {
    asm volatile("tcgen05.alloc.cta_group::1.sync.aligned.shared::cta.b32 [%0], %1;"
                 :: "r"(smem_dst), "r"(ncols) : "memory");
}
__device__ __forceinline__ void tmem_dealloc(u32 tmem, u32 ncols) {
    asm volatile("tcgen05.dealloc.cta_group::1.sync.aligned.b32 %0, %1;" :: "r"(tmem), "r"(ncols));
}
__device__ __forceinline__ void mma_f16_ss(u32 d_tmem, ull a_desc, ull b_desc, u32 idesc, int accum) {
    u32 z = 0;
    asm volatile(
        "{\n\t.reg .pred p;\n\tsetp.ne.u32 p, %5, 0;\n\t"
        "tcgen05.mma.cta_group::1.kind::f16 [%0], %1, %2, %3, {%4, %4, %4, %4}, p;\n\t}"
        :: "r"(d_tmem), "l"(a_desc), "l"(b_desc), "r"(idesc), "r"(z), "r"((u32)accum) : "memory");
}
__device__ __forceinline__ void mma_commit(u32 mbar) {
    asm volatile("tcgen05.commit.cta_group::1.mbarrier::arrive::one.shared::cluster.b64 [%0];"
                 :: "r"(mbar) : "memory");
}
__device__ __forceinline__ void fence_async_proxy() {
    asm volatile("fence.proxy.async.shared::cta;" ::: "memory");
}
__device__ __forceinline__ void tc_fence_after() {
    asm volatile("tcgen05.fence::after_thread_sync;" ::: "memory");
}
__device__ __forceinline__ void tmem_wait_ld() {
    asm volatile("tcgen05.wait::ld.sync.aligned;" ::: "memory");
}

#define LDTM32(r, addr)                                                      \
    asm volatile("tcgen05.ld.sync.aligned.32x32b.x32.b32 "                   \
        "{%0, %1, %2, %3, %4, %5, %6, %7, %8, %9, %10, %11, %12, %13, %14, %15, " \
        " %16, %17, %18, %19, %20, %21, %22, %23, %24, %25, %26, %27, %28, %29, %30, %31}, [%32];" \
        : "=r"((r)[0]), "=r"((r)[1]), "=r"((r)[2]), "=r"((r)[3]),            \
          "=r"((r)[4]), "=r"((r)[5]), "=r"((r)[6]), "=r"((r)[7]),            \
          "=r"((r)[8]), "=r"((r)[9]), "=r"((r)[10]), "=r"((r)[11]),          \
          "=r"((r)[12]), "=r"((r)[13]), "=r"((r)[14]), "=r"((r)[15]),        \
          "=r"((r)[16]), "=r"((r)[17]), "=r"((r)[18]), "=r"((r)[19]),        \
          "=r"((r)[20]), "=r"((r)[21]), "=r"((r)[22]), "=r"((r)[23]),        \
          "=r"((r)[24]), "=r"((r)[25]), "=r"((r)[26]), "=r"((r)[27]),        \
          "=r"((r)[28]), "=r"((r)[29]), "=r"((r)[30]), "=r"((r)[31])         \
        : "r"(addr))

__device__ __forceinline__ u32 sw128(u32 off) { return off ^ ((off >> 3) & 0x70); }
__device__ __forceinline__ u32 sw64(u32 off)  { return off ^ ((off >> 3) & 0x30); }

#define DESC_BASE   ((2ull << 61) | (1ull << 46) | (64ull << 32) | (1ull << 16))
#define DESC_BASE64 ((4ull << 61) | (1ull << 46) | (32ull << 32) | (1ull << 16))
__device__ __forceinline__ ull mk_desc(u32 addr)   { return DESC_BASE   | ((ull)(addr >> 4) & 0x3FFF); }
__device__ __forceinline__ ull mk_desc64(u32 addr) { return DESC_BASE64 | ((ull)(addr >> 4) & 0x3FFF); }

// idesc: F32 accum, BF16 x BF16, M=128, N=256
#define MMA_IDESC 0x8400490u
#endif  // TCOK

// k6 smem layout (K=64 windows, SW128)
#define SM_TPTR 0
#define SM_MBAR 8
#define SM_AH 1024
#define SM_AL (1024 + 16384)
#define SM_BH (1024 + 32768)
#define SM_BL (1024 + 65536)
#define SMEM_TOTAL (1024 + 98304)

// k1 smem layout (K=32 windows, SW64; fp32 staging + operand bufs) — 2 CTAs/SM
#define K1_STGK 256                        // 32 x 132 f32 = 16896
#define K1_STGV 17152                      // 32 x 260 f32 = 33280
#define K1_AH   51200                      // 128 x 64B = 8192
#define K1_AL   (51200 + 8192)
#define K1_BH   (51200 + 16384)            // 256 x 64B = 16384
#define K1_BL   (51200 + 32768)
#define K1_TOTAL (51200 + 49152)           // 100352 B

// ---------------- mask detect (parallel) + canonicalize (+cm) ----------------
__global__ void k_detect(const unsigned char* __restrict__ raw) {
    // check byte offsets p = 4*idx+1 over the first 64KB; nonzero => byte mask
    int idx = blockIdx.x * blockDim.x + threadIdx.x;   // < 16384
    if (raw[idx * 4 + 1] != 0) atomicOr(&g_kind, 1);
}

__global__ void k_maskconv(const void* __restrict__ rawv) {
    int n = blockIdx.x * blockDim.x + threadIdx.x;
    bool padded;
    if (g_kind) padded = ((const unsigned char*)rawv)[n] != 0;
    else        padded = ((const unsigned int*)rawv)[n] != 0u;
    float m = padded ? 0.f : 1.f;
    g_m[n] = m;
    float s = m;
#pragma unroll
    for (int o = 16; o > 0; o >>= 1) s += __shfl_xor_sync(0xffffffffu, s, o);
    __shared__ float red[8];
    int wid = threadIdx.x >> 5, lane = threadIdx.x & 31;
    if (lane == 0) red[wid] = s;
    __syncthreads();
    if (threadIdx.x == 0) {
        float t = 0.f;
        for (int i = 0; i < 8; i++) t += red[i];
        atomicAdd(&g_cm[n >> 13], t);
    }
}

__global__ void k_zero() {
    int i = blockIdx.x * blockDim.x + threadIdx.x;
    if (i < B_ * D_ * D_) g_S[i] = 0.f;
    if (i < B_ * D_) { g_rk[i] = 0.f; g_rv[i] = 0.f; }
    if (i < B_) g_cm[i] = 0.f;
    if (i == 0) g_kind = 0;
}

// ---------------- k1: S[b] += K_m^T V via tcgen05, K=32 windows, SW64 --------
// grid (16 chunks, 2 slabs, B), 256 threads, 2 CTAs/SM. 16 windows of n=32.
__global__ void __launch_bounds__(256, 2)
k1_mma(const float* __restrict__ key, const float* __restrict__ value) {
#if TCOK
    extern __shared__ char smem[];
    const u32 sb = smem_u32(smem);
    const int tid = threadIdx.x, wid = tid >> 5, lid = tid & 31;
    const int b = blockIdx.z, slab = blockIdx.y, chunk = blockIdx.x;
    const int d0 = slab * 128;
    const int n_start = chunk * 512;

    if (wid == 0) tmem_alloc(sb + SM_TPTR, 256);
    if (tid == 0) mbar_init(sb + SM_MBAR, 1);
    __syncthreads();
    u32 tbase;
    asm volatile("ld.shared.b32 %0, [%1];" : "=r"(tbase) : "r"(sb + SM_TPTR));

    const ull dAH = mk_desc64(sb + K1_AH), dAL = mk_desc64(sb + K1_AL);
    const ull dBH = mk_desc64(sb + K1_BH), dBL = mk_desc64(sb + K1_BL);
    float* stgK = (float*)(smem + K1_STGK);    // [32 n][132] masked key (d cols)
    float* stgV = (float*)(smem + K1_STGV);    // [32 n][260] raw value (e cols)

    float sk4[4] = {0.f, 0.f, 0.f, 0.f};       // masked key col sums (d = d0 + (tid&31)*4 + j)
    float sv4[4] = {0.f, 0.f, 0.f, 0.f};       // masked value col sums (e = (tid&63)*4 + j)

    for (int c = 0; c < 16; c++) {
        const int n = n_start + c * 32;
        const float* kp = key + ((size_t)b * N_ + n) * D_ + d0;
        const float* vp = value + ((size_t)b * N_ + n) * D_;
        const float* mp = g_m + (size_t)b * N_ + n;
        // stage key (masked) : 32 x 128 f32 = 1024 f4
#pragma unroll
        for (int k = 0; k < 4; k++) {
            int i = tid + 256 * k;
            int r = i >> 5, cc = i & 31;      // cc = tid&31 (fixed per thread)
            float m = mp[r];
            float4 v = *(const float4*)(kp + (size_t)r * D_ + cc * 4);
            v.x *= m; v.y *= m; v.z *= m; v.w *= m;
            *(float4*)&stgK[r * 132 + cc * 4] = v;
            sk4[0] += v.x; sk4[1] += v.y; sk4[2] += v.z; sk4[3] += v.w;
        }
        // stage value (raw) : 32 x 256 f32 = 2048 f4
#pragma unroll
        for (int k = 0; k < 8; k++) {
            int i = tid + 256 * k;
            int r = i >> 6, cc = i & 63;      // cc = tid&63 (fixed per thread)
            float m = mp[r];
            float4 v = *(const float4*)(vp + (size_t)r * D_ + cc * 4);
            *(float4*)&stgV[r * 260 + cc * 4] = v;
            sv4[0] += m * v.x; sv4[1] += m * v.y; sv4[2] += m * v.z; sv4[3] += m * v.w;
        }
        __syncthreads();
        if (c >= 1) mbar_wait(sb + SM_MBAR, (u32)((c - 1) & 1));  // operand bufs free

        // convert A: 128 d-rows x 32 n -> SW64 (warp reads consecutive r: conflict-free)
#pragma unroll
        for (int k = 0; k < 2; k++) {
            int i = tid + 256 * k;
            int r = i & 127, g = i >> 7;      // g in 0..3 (8-n group)
            uint4 hv, lv;
            cvt2(stgK[(g * 8 + 0) * 132 + r], stgK[(g * 8 + 1) * 132 + r], hv.x, lv.x);
            cvt2(stgK[(g * 8 + 2) * 132 + r], stgK[(g * 8 + 3) * 132 + r], hv.y, lv.y);
            cvt2(stgK[(g * 8 + 4) * 132 + r], stgK[(g * 8 + 5) * 132 + r], hv.z, lv.z);
            cvt2(stgK[(g * 8 + 6) * 132 + r], stgK[(g * 8 + 7) * 132 + r], hv.w, lv.w);
            u32 sw = sw64((u32)(r * 64 + g * 16));
            *(uint4*)(smem + K1_AH + sw) = hv;
            *(uint4*)(smem + K1_AL + sw) = lv;
        }
        // convert B: 256 e-rows x 32 n -> SW64
#pragma unroll
        for (int k = 0; k < 4; k++) {
            int i = tid + 256 * k;
            int r = i & 255, g = i >> 8;
            uint4 hv, lv;
            cvt2(stgV[(g * 8 + 0) * 260 + r], stgV[(g * 8 + 1) * 260 + r], hv.x, lv.x);
            cvt2(stgV[(g * 8 + 2) * 260 + r], stgV[(g * 8 + 3) * 260 + r], hv.y, lv.y);
            cvt2(stgV[(g * 8 + 4) * 260 + r], stgV[(g * 8 + 5) * 260 + r], hv.z, lv.z);
            cvt2(stgV[(g * 8 + 6) * 260 + r], stgV[(g * 8 + 7) * 260 + r], hv.w, lv.w);
            u32 sw = sw64((u32)(r * 64 + g * 16));
            *(uint4*)(smem + K1_BH + sw) = hv;
            *(uint4*)(smem + K1_BL + sw) = lv;
        }
        __syncthreads();
        fence_async_proxy();
        if (wid == 0 && elect1()) {
#pragma unroll
            for (int ks = 0; ks < 2; ks++) {
                ull o = (ull)(ks * 2);
                mma_f16_ss(tbase, dAH + o, dBH + o, MMA_IDESC, !(c == 0 && ks == 0));
                mma_f16_ss(tbase, dAH + o, dBL + o, MMA_IDESC, 1);
                mma_f16_ss(tbase, dAL + o, dBH + o, MMA_IDESC, 1);
            }
            mma_commit(sb + SM_MBAR);
        }
        // staging writes of next window are safe: all threads passed the
        // post-convert barrier (staging reads done); MMA reads only A/B bufs.
    }
    mbar_wait(sb + SM_MBAR, 1);   // commit 15: parity 15&1
    tc_fence_after();

    if (wid < 4) {
        float* dst0 = g_S + ((size_t)b * D_ + d0 + wid * 32 + lid) * D_;
#pragma unroll
        for (int blk = 0; blk < 8; blk++) {
            u32 r[32];
            LDTM32(r, tbase + blk * 32);
            tmem_wait_ld();
#pragma unroll
            for (int cc = 0; cc < 32; cc++)
                atomicAdd(dst0 + blk * 32 + cc, __uint_as_float(r[cc]));
        }
    }
    __syncthreads();
    // side-sum reductions (reuse staging)
    *(float4*)&stgK[tid * 4] = make_float4(sk4[0], sk4[1], sk4[2], sk4[3]);
    *(float4*)&stgV[tid * 4] = make_float4(sv4[0], sv4[1], sv4[2], sv4[3]);
    __syncthreads();
    if (tid < 128) {                 // d-output t: cc=t>>2, j=t&3; 8 groups
        int cc = tid >> 2, j = tid & 3;
        float s = 0.f;
#pragma unroll
        for (int g = 0; g < 8; g++) s += stgK[(g * 32 + cc) * 4 + j];
        atomicAdd(&g_rk[b * D_ + d0 + tid], s);
    }
    if (slab == 0) {                 // e-output t<256: 4 groups
        int cc = tid >> 2, j = tid & 3;
        float s = 0.f;
#pragma unroll
        for (int g = 0; g < 4; g++) s += stgV[(g * 64 + cc) * 4 + j];
        atomicAdd(&g_rv[b * D_ + tid], s);
    }
    __syncthreads();
    if (tid == 0) mbar_inval(sb + SM_MBAR);
    __syncthreads();
    if (wid == 0) tmem_dealloc(tbase, 256);
#else
    // FFMA fallback (non-'a' PTX stage only)
    const int tid = threadIdx.x;
    const int b = blockIdx.z, d0 = blockIdx.y * 128, chunk = blockIdx.x;
    const int n_start = chunk * 512;
    for (int idx = tid; idx < 128 * 256; idx += 256) {
        int d = d0 + (idx >> 8), e = idx & 255;
        float acc = 0.f;
        for (int n = n_start; n < n_start + 512; n++) {
            float m = g_m[(size_t)b * N_ + n];
            acc += m * key[((size_t)b * N_ + n) * D_ + d] * value[((size_t)b * N_ + n) * D_ + e];
        }
        atomicAdd(&g_S[((size_t)b * D_ + d) * D_ + e], acc);
    }
    if (tid < 128) {
        float s = 0.f;
        for (int n = n_start; n < n_start + 512; n++)
            s += g_m[(size_t)b * N_ + n] * key[((size_t)b * N_ + n) * D_ + d0 + tid];
        atomicAdd(&g_rk[b * D_ + d0 + tid], s);
    }
    if (blockIdx.y == 0) {
        float s = 0.f;
        for (int n = n_start; n < n_start + 512; n++)
            s += g_m[(size_t)b * N_ + n] * value[((size_t)b * N_ + n) * D_ + tid];
        atomicAdd(&g_rv[b * D_ + tid], s);
    }
#endif
}

// ---------------- k_uw: u = Wk@rk, w = Wv@rv ----------------
__global__ void k_uw(const float* __restrict__ Wk, const float* __restrict__ Wv) {
    int b = blockIdx.x, d = threadIdx.x;
    float su = 0.f, sw = 0.f;
    for (int i = 0; i < D_; i++) {
        su += Wk[d * D_ + i] * g_rk[b * D_ + i];
        sw += Wv[d * D_ + i] * g_rv[b * D_ + i];
    }
    g_u[b * D_ + d] = su;
    g_w[b * D_ + d] = sw;
}

// ---------------- k2: T1 = Wk @ S ----------------
__global__ void __launch_bounds__(256, 1)
k2_T1(const float* __restrict__ Wk) {
    const int b = blockIdx.y, d0 = blockIdx.x * 16;
    const int tid = threadIdx.x, tx = tid & 15, ty = tid >> 4;
    __shared__ float sA[16][16];
    __shared__ float sB[16][256];
    ull acc[8];
#pragma unroll
    for (int p = 0; p < 8; p++) acc[p] = 0ull;
    const float* Sb = g_S + b * D_ * D_;
    for (int i0 = 0; i0 < D_; i0 += 16) {
        __syncthreads();
        if (tid < 64) {
            int r = tid >> 2, q = tid & 3;
            *(float4*)&sA[r][q * 4] = *(const float4*)(Wk + (size_t)(d0 + r) * D_ + i0 + q * 4);
        }
#pragma unroll
        for (int i = 0; i < 4; i++) {
            int idx = tid + 256 * i;
            int r = idx >> 6, q = idx & 63;
            *(float4*)&sB[r][q * 4] = *(const float4*)(Sb + (size_t)(i0 + r) * D_ + q * 4);
        }
        __syncthreads();
#pragma unroll
        for (int ii = 0; ii < 16; ii++) {
            float a = sA[ty][ii];
            ull a2 = pack2(a, a);
#pragma unroll
            for (int p = 0; p < 8; p++)
                acc[p] = ffma2(a2, *(const ull*)&sB[ii][2 * tx + 32 * p], acc[p]);
        }
    }
    float* T1b = g_T1 + b * D_ * D_;
    int row = d0 + ty;
#pragma unroll
    for (int p = 0; p < 8; p++) {
        float lo, hi; unpack2(acc[p], lo, hi);
        *(float2*)&T1b[row * D_ + 2 * tx + 32 * p] = make_float2(lo, hi);
    }
}

// ---------------- k3: A = (T1 @ Wv^T + rank-1) / sqrt(8) ----------------
__global__ void __launch_bounds__(256, 1)
k3_A(const float* __restrict__ Wv, const float* __restrict__ bk,
     const float* __restrict__ bv) {
    const int b = blockIdx.y, d0 = blockIdx.x * 16;
    const int tid = threadIdx.x, tx = tid & 15, ty = tid >> 4;
    __shared__ float sA[16][16];
    __shared__ float sB[16][258];
    ull acc[8];
#pragma unroll
    for (int p = 0; p < 8; p++) acc[p] = 0ull;
    const float* T1b = g_T1 + b * D_ * D_;
    for (int j0 = 0; j0 < D_; j0 += 16) {
        __syncthreads();
        if (tid < 64) {
            int r = tid >> 2, q = tid & 3;
            *(float4*)&sA[r][q * 4] = *(const float4*)(T1b + (size_t)(d0 + r) * D_ + j0 + q * 4);
        }
#pragma unroll
        for (int i = 0; i < 4; i++) {
            int idx = tid + 256 * i;
            int q = idx & 3, e = idx >> 2;
            float4 v = *(const float4*)(Wv + (size_t)e * D_ + j0 + q * 4);
            sB[q * 4 + 0][e] = v.x; sB[q * 4 + 1][e] = v.y;
            sB[q * 4 + 2][e] = v.z; sB[q * 4 + 3][e] = v.w;
        }
        __syncthreads();
#pragma unroll
        for (int jj = 0; jj < 16; jj++) {
            float a = sA[ty][jj];
            ull a2 = pack2(a, a);
#pragma unroll
            for (int p = 0; p < 8; p++)
                acc[p] = ffma2(a2, *(const ull*)&sB[jj][2 * tx + 32 * p], acc[p]);
        }
    }
    const int d = d0 + ty;
    const float u_d = g_u[b * D_ + d], bk_d = bk[d], cmv = g_cm[b];
    const float inv = 0.3535533905932738f;
    float* Ab = g_A + b * D_ * D_;
#pragma unroll
    for (int p = 0; p < 8; p++) {
        float lo, hi; unpack2(acc[p], lo, hi);
        int e = 2 * tx + 32 * p;
        float bv0 = bv[e], bv1 = bv[e + 1];
        float w0 = g_w[b * D_ + e], w1 = g_w[b * D_ + e + 1];
        lo = (lo + u_d * bv0 + bk_d * w0 + cmv * bk_d * bv0) * inv;
        hi = (hi + u_d * bv1 + bk_d * w1 + cmv * bk_d * bv1) * inv;
        *(float2*)&Ab[d * D_ + e] = make_float2(lo, hi);
    }
}

// ---------------- k4: column softmax + t = bq^T aw ----------------
__global__ void k4_softmax(const float* __restrict__ bq) {
    const int b = blockIdx.y;
    const int w = threadIdx.x >> 5, lane = threadIdx.x & 31;
    const int e = blockIdx.x * 8 + w;
    float* col = g_A + b * D_ * D_ + e;
    float v[8];
#pragma unroll
    for (int s = 0; s < 8; s++) v[s] = col[(lane + 32 * s) * D_];
    float mx = v[0];
#pragma unroll
    for (int s = 1; s < 8; s++) mx = fmaxf(mx, v[s]);
#pragma unroll
    for (int o = 16; o > 0; o >>= 1) mx = fmaxf(mx, __shfl_xor_sync(0xffffffffu, mx, o));
    float sum = 0.f;
#pragma unroll
    for (int s = 0; s < 8; s++) { v[s] = expf(v[s] - mx); sum += v[s]; }
#pragma unroll
    for (int o = 16; o > 0; o >>= 1) sum += __shfl_xor_sync(0xffffffffu, sum, o);
    const float isum = 1.f / sum;
    float tacc = 0.f;
#pragma unroll
    for (int s = 0; s < 8; s++) {
        float p = v[s] * isum;
        col[(lane + 32 * s) * D_] = p;
        tacc += p * bq[lane + 32 * s];
    }
#pragma unroll
    for (int o = 16; o > 0; o >>= 1) tacc += __shfl_xor_sync(0xffffffffu, tacc, o);
    if (lane == 0) g_t[b * D_ + e] = tacc;
}

// ---------------- k5: M^T[e][i] = sum_d Wq[d][i] aw[d][e] -> bf16 hi/lo ------
__global__ void __launch_bounds__(256, 1)
k5_M(const float* __restrict__ Wq) {
    const int b = blockIdx.y, i0 = blockIdx.x * 16;
    const int tid = threadIdx.x, tx = tid & 15, ty = tid >> 4;
    __shared__ float sA[16][17];
    __shared__ float sB[16][256];
    ull acc[8];
#pragma unroll
    for (int p = 0; p < 8; p++) acc[p] = 0ull;
    const float* awb = g_A + b * D_ * D_;
    for (int dd0 = 0; dd0 < D_; dd0 += 16) {
        __syncthreads();
        if (tid < 64) {
            int r = tid >> 2, q = tid & 3;
            float4 v = *(const float4*)(Wq + (size_t)(dd0 + r) * D_ + i0 + q * 4);
            sA[q * 4 + 0][r] = v.x; sA[q * 4 + 1][r] = v.y;
            sA[q * 4 + 2][r] = v.z; sA[q * 4 + 3][r] = v.w;
        }
#pragma unroll
        for (int i = 0; i < 4; i++) {
            int idx = tid + 256 * i;
            int r = idx >> 6, q = idx & 63;
            *(float4*)&sB[r][q * 4] = *(const float4*)(awb + (size_t)(dd0 + r) * D_ + q * 4);
        }
        __syncthreads();
#pragma unroll
        for (int dd = 0; dd < 16; dd++) {
            float a = sA[ty][dd];
            ull a2 = pack2(a, a);
#pragma unroll
            for (int p = 0; p < 8; p++)
                acc[p] = ffma2(a2, *(const ull*)&sB[dd][2 * tx + 32 * p], acc[p]);
        }
    }
    const int row = i0 + ty;
#pragma unroll
    for (int p = 0; p < 8; p++) {
        float lo, hi; unpack2(acc[p], lo, hi);
        int e0 = 2 * tx + 32 * p, e1 = e0 + 1;
        __nv_bfloat16 h0 = __float2bfloat16(lo);
        __nv_bfloat16 h1 = __float2bfloat16(hi);
        g_MTH[((size_t)b * D_ + e0) * D_ + row] = h0;
        g_MTL[((size_t)b * D_ + e0) * D_ + row] = __float2bfloat16(lo - __bfloat162float(h0));
        g_MTH[((size_t)b * D_ + e1) * D_ + row] = h1;
        g_MTL[((size_t)b * D_ + e1) * D_ + row] = __float2bfloat16(hi - __bfloat162float(h1));
    }
}

// ---------------- k6: out = query @ M + t via tcgen05 (256 thr, 2 CTAs/SM) ---
__global__ void __launch_bounds__(256, 2)
k6_mma(const float* __restrict__ query, float* __restrict__ out) {
#if TCOK
    extern __shared__ char smem[];
    const u32 sb = smem_u32(smem);
    const int tid = threadIdx.x, wid = tid >> 5, lid = tid & 31;
    const int b = blockIdx.y, n0 = blockIdx.x * 128;

    if (wid == 0) tmem_alloc(sb + SM_TPTR, 256);
    if (tid == 0) mbar_init(sb + SM_MBAR, 1);
    __syncthreads();
    u32 tbase;
    asm volatile("ld.shared.b32 %0, [%1];" : "=r"(tbase) : "r"(sb + SM_TPTR));

    const ull dAH = mk_desc(sb + SM_AH), dAL = mk_desc(sb + SM_AL);
    const ull dBH = mk_desc(sb + SM_BH), dBL = mk_desc(sb + SM_BL);
    const float* qb = query + ((size_t)b * N_ + n0) * D_;
    const size_t bbase0 = (size_t)b * D_ * D_;

    for (int c = 0; c < 4; c++) {
        if (c >= 1) mbar_wait(sb + SM_MBAR, (u32)((c - 1) & 1));
        const int dc = c * 64;
#pragma unroll
        for (int i = tid; i < 1024; i += 256) {           // A: q fp32 -> hi/lo inline
            int r = i >> 3, c16 = i & 7;
            const float* src = qb + (size_t)r * D_ + dc + c16 * 8;
            float4 a = *(const float4*)(src);
            float4 d = *(const float4*)(src + 4);
            uint4 hv, lv;
            cvt2(a.x, a.y, hv.x, lv.x);
            cvt2(a.z, a.w, hv.y, lv.y);
            cvt2(d.x, d.y, hv.z, lv.z);
            cvt2(d.z, d.w, hv.w, lv.w);
            u32 sw = sw128((u32)(r * 128 + c16 * 16));
            *(uint4*)(smem + SM_AH + sw) = hv;
            *(uint4*)(smem + SM_AL + sw) = lv;
        }
#pragma unroll
        for (int i = tid; i < 2048; i += 256) {           // B: M^T bf16 rows
            int r = i >> 3, c16 = i & 7;
            size_t off = bbase0 + (size_t)r * D_ + dc + c16 * 8;
            u32 sw = sw128((u32)(r * 128 + c16 * 16));
            *(uint4*)(smem + SM_BH + sw) = *(const uint4*)(g_MTH + off);
            *(uint4*)(smem + SM_BL + sw) = *(const uint4*)(g_MTL + off);
        }
        __syncthreads();
        fence_async_proxy();
        if (wid == 0 && elect1()) {
#pragma unroll
            for (int ks = 0; ks < 4; ks++) {
                ull o = (ull)(ks * 2);
                mma_f16_ss(tbase, dAH + o, dBH + o, MMA_IDESC, !(c == 0 && ks == 0));
                mma_f16_ss(tbase, dAH + o, dBL + o, MMA_IDESC, 1);
                mma_f16_ss(tbase, dAL + o, dBH + o, MMA_IDESC, 1);
            }
            mma_commit(sb + SM_MBAR);
        }
        __syncthreads();
    }
    mbar_wait(sb + SM_MBAR, 1);    // commit 3: parity 3&1
    tc_fence_after();

    float* stage = (float*)(smem + 1024);   // [128][68]
    for (int cb = 0; cb < 4; cb++) {
        __syncthreads();
        if (wid < 4) {
            u32 r0[32], r1[32];
            LDTM32(r0, tbase + cb * 64);
            LDTM32(r1, tbase + cb * 64 + 32);
            tmem_wait_ld();
            float* srow = stage + (wid * 32 + lid) * 68;
#pragma unroll
            for (int cc = 0; cc < 32; cc++) {
                srow[cc] = __uint_as_float(r0[cc]);
                srow[32 + cc] = __uint_as_float(r1[cc]);
            }
        }
        __syncthreads();
#pragma unroll
        for (int i = tid; i < 2048; i += 256) {
            int r = i >> 4, c4 = i & 15;
            float4 v = *(float4*)(stage + r * 68 + c4 * 4);
            int e = cb * 64 + c4 * 4;
            v.x += g_t[b * D_ + e];
            v.y += g_t[b * D_ + e + 1];
            v.z += g_t[b * D_ + e + 2];
            v.w += g_t[b * D_ + e + 3];
            *(float4*)(out + ((size_t)b * N_ + n0 + r) * D_ + e) = v;
        }
    }
    __syncthreads();
    if (tid == 0) mbar_inval(sb + SM_MBAR);
    __syncthreads();
    if (wid == 0) tmem_dealloc(tbase, 256);
#else
    // FFMA fallback
    const int tid = threadIdx.x;
    const int b = blockIdx.y, n0 = blockIdx.x * 128;
    for (int idx = tid; idx < 128 * 256; idx += 256) {
        int n = n0 + (idx >> 8), e = idx & 255;
        const float* q = query + ((size_t)b * N_ + n) * D_;
        const __nv_bfloat16* mh = g_MTH + ((size_t)b * D_ + e) * D_;
        const __nv_bfloat16* ml = g_MTL + ((size_t)b * D_ + e) * D_;
        float acc = g_t[b * D_ + e];
        for (int d = 0; d < D_; d++)
            acc += q[d] * (__bfloat162float(mh[d]) + __bfloat162float(ml[d]));
        out[((size_t)b * N_ + n) * D_ + e] = acc;
    }
#endif
}

// ---------------- launch ----------------
extern "C" void kernel_launch(void* const* d_in, const int* in_sizes, int n_in,
                              void* d_out, int out_size) {
    const float* query = (const float*)d_in[0];
    const float* key   = (const float*)d_in[1];
    const float* value = (const float*)d_in[2];
    const void*  maskraw = d_in[3];
    int o = (n_in >= 11) ? 5 : 4;
    const float* Wq = (const float*)d_in[o + 0];
    const float* bq = (const float*)d_in[o + 1];
    const float* Wk = (const float*)d_in[o + 2];
    const float* bk = (const float*)d_in[o + 3];
    const float* Wv = (const float*)d_in[o + 4];
    const float* bv = (const float*)d_in[o + 5];
    float* out = (float*)d_out;
    (void)in_sizes; (void)out_size;

    cudaFuncSetAttribute(k1_mma, cudaFuncAttributeMaxDynamicSharedMemorySize, K1_TOTAL);
    cudaFuncSetAttribute(k6_mma, cudaFuncAttributeMaxDynamicSharedMemorySize, SMEM_TOTAL);

    k_zero<<<(B_ * D_ * D_ + 255) / 256, 256>>>();
    k_detect<<<64, 256>>>((const unsigned char*)maskraw);
    k_maskconv<<<(B_ * N_) / 256, 256>>>(maskraw);
    k1_mma<<<dim3(16, 2, B_), 256, K1_TOTAL>>>(key, value);
    k_uw<<<B_, 256>>>(Wk, Wv);
    k2_T1<<<dim3(16, B_), 256>>>(Wk);
    k3_A<<<dim3(16, B_), 256>>>(Wv, bk, bv);
    k4_softmax<<<dim3(32, B_), 256>>>(bq);
    k5_M<<<dim3(16, B_), 256>>>(Wq);
    k6_mma<<<dim3(64, B_), 256, SMEM_TOTAL>>>(query, out);
}

// round 9
// speedup vs baseline: 1.1437x; 1.1437x over previous
#include <cuda_runtime.h>
#include <cuda_bf16.h>
#include <cstdint>
#include <cstddef>

#define B_ 8
#define N_ 8192
#define D_ 256

typedef unsigned long long ull;
typedef unsigned int u32;

#if !defined(__CUDA_ARCH__) || defined(__CUDA_ARCH_FEAT_SM103_ALL) || defined(__CUDA_ARCH_FEAT_SM100_ALL) || defined(__CUDA_ARCH_FEAT_SM101_ALL)
#define TCOK 1
#else
#define TCOK 0
#endif

// ---------------- device scratch ----------------
__device__ __nv_bfloat16 g_MTH[B_ * D_ * D_];   // (Wq^T aw)^T hi [b][e][i]
__device__ __nv_bfloat16 g_MTL[B_ * D_ * D_];
__device__ float g_S[B_ * D_ * D_];
__device__ float g_T1[B_ * D_ * D_];
__device__ float g_A[B_ * D_ * D_];
__device__ float g_rk[B_ * D_];
__device__ float g_rv[B_ * D_];
__device__ float g_u[B_ * D_];
__device__ float g_w[B_ * D_];
__device__ float g_t[B_ * D_];
__device__ float g_cm[B_];
__device__ int   g_kind;
__device__ float g_m[B_ * N_];

// ---------------- scalar helpers ----------------
__device__ __forceinline__ ull pack2(float lo, float hi) {
    ull r; asm("mov.b64 %0, {%1,%2};" : "=l"(r) : "f"(lo), "f"(hi)); return r;
}
__device__ __forceinline__ void unpack2(ull v, float& lo, float& hi) {
    asm("mov.b64 {%0,%1}, %2;" : "=f"(lo), "=f"(hi) : "l"(v));
}
__device__ __forceinline__ ull ffma2(ull a, ull b, ull c) {
    ull d; asm("fma.rn.f32x2 %0, %1, %2, %3;" : "=l"(d) : "l"(a), "l"(b), "l"(c)); return d;
}
__device__ __forceinline__ u32 prmt7632(u32 a, u32 b) {
    u32 d; asm("prmt.b32 %0, %1, %2, 0x7632;" : "=r"(d) : "r"(a), "r"(b)); return d;
}
// f32 pair -> bf16x2 hi (truncated) + bf16x2 lo (residual, truncated). err ~2^-16.
__device__ __forceinline__ void cvt2(float x0, float x1, u32& h2, u32& l2) {
    u32 u0 = __float_as_uint(x0), u1 = __float_as_uint(x1);
    h2 = prmt7632(u0, u1);
    float l0 = x0 - __uint_as_float(u0 & 0xFFFF0000u);
    float l1 = x1 - __uint_as_float(u1 & 0xFFFF0000u);
    l2 = prmt7632(__float_as_uint(l0), __float_as_uint(l1));
}

// ---------------- tcgen05 / async helpers (guarded) ----------------
#if TCOK
__device__ __forceinline__ u32 smem_u32(const void* p) {
    u32 a; asm("{ .reg .u64 t; cvta.to.shared.u64 t, %1; cvt.u32.u64 %0, t; }" : "=r"(a) : "l"(p));
    return a;
}
__device__ __forceinline__ int elect1() {
    u32 p;
    asm volatile("{\n\t.reg .pred p;\n\telect.sync _|p, 0xFFFFFFFF;\n\tselp.b32 %0, 1, 0, p;\n\t}" : "=r"(p));
    return (int)p;
}
__device__ __forceinline__ void cp16(u32 dst, const void* src) {
    asm volatile("cp.async.cg.shared.global [%0], [%1], 16;" :: "r"(dst), "l"(src) : "memory");
}
__device__ __forceinline__ void cp_commit() {
    asm volatile("cp.async.commit_group;" ::: "memory");
}
template <int N>
__device__ __forceinline__ void cp_wait() {
    asm volatile("cp.async.wait_group %0;" :: "n"(N) : "memory");
}
__device__ __forceinline__ void mbar_init(u32 mbar, u32 cnt) {
    asm volatile("mbarrier.init.shared.b64 [%0], %1;" :: "r"(mbar), "r"(cnt) : "memory");
}
__device__ __forceinline__ void mbar_inval(u32 mbar) {
    asm volatile("mbarrier.inval.shared.b64 [%0];" :: "r"(mbar) : "memory");
}
__device__ __forceinline__ void mbar_wait(u32 mbar, u32 parity) {
    asm volatile(
        "{\n\t.reg .pred P;\n\t"
        "WL_%=:\n\t"
        "mbarrier.try_wait.parity.acquire.cta.shared::cta.b64 P, [%0], %1, 0x989680;\n\t"
        "@P bra WD_%=;\n\t"
        "bra.uni WL_%=;\n\t"
        "WD_%=:\n\t}"
        :: "r"(mbar), "r"(parity) : "memory");
}
__device__ __forceinline__ void tmem_alloc(u32 smem_dst, u32 ncols) {
    asm volatile("tcgen05.alloc.cta_group::1.sync.aligned.shared::cta.b32 [%0], %1;"
                 :: "r"(smem_dst), "r"(ncols) : "memory");
}
__device__ __forceinline__ void tmem_dealloc(u32 tmem, u32 ncols) {
    asm volatile("tcgen05.dealloc.cta_group::1.sync.aligned.b32 %0, %1;" :: "r"(tmem), "r"(ncols));
}
__device__ __forceinline__ void mma_f16_ss(u32 d_tmem, ull a_desc, ull b_desc, u32 idesc, int accum) {
    u32 z = 0;
    asm volatile(
        "{\n\t.reg .pred p;\n\tsetp.ne.u32 p, %5, 0;\n\t"
        "tcgen05.mma.cta_group::1.kind::f16 [%0], %1, %2, %3, {%4, %4, %4, %4}, p;\n\t}"
        :: "r"(d_tmem), "l"(a_desc), "l"(b_desc), "r"(idesc), "r"(z), "r"((u32)accum) : "memory");
}
__device__ __forceinline__ void mma_commit(u32 mbar) {
    asm volatile("tcgen05.commit.cta_group::1.mbarrier::arrive::one.shared::cluster.b64 [%0];"
                 :: "r"(mbar) : "memory");
}
__device__ __forceinline__ void fence_async_proxy() {
    asm volatile("fence.proxy.async.shared::cta;" ::: "memory");
}
__device__ __forceinline__ void tc_fence_after() {
    asm volatile("tcgen05.fence::after_thread_sync;" ::: "memory");
}
__device__ __forceinline__ void tmem_wait_ld() {
    asm volatile("tcgen05.wait::ld.sync.aligned;" ::: "memory");
}

#define LDTM32(r, addr)                                                      \
    asm volatile("tcgen05.ld.sync.aligned.32x32b.x32.b32 "                   \
        "{%0, %1, %2, %3, %4, %5, %6, %7, %8, %9, %10, %11, %12, %13, %14, %15, " \
        " %16, %17, %18, %19, %20, %21, %22, %23, %24, %25, %26, %27, %28, %29, %30, %31}, [%32];" \
        : "=r"((r)[0]), "=r"((r)[1]), "=r"((r)[2]), "=r"((r)[3]),            \
          "=r"((r)[4]), "=r"((r)[5]), "=r"((r)[6]), "=r"((r)[7]),            \
          "=r"((r)[8]), "=r"((r)[9]), "=r"((r)[10]), "=r"((r)[11]),          \
          "=r"((r)[12]), "=r"((r)[13]), "=r"((r)[14]), "=r"((r)[15]),        \
          "=r"((r)[16]), "=r"((r)[17]), "=r"((r)[18]), "=r"((r)[19]),        \
          "=r"((r)[20]), "=r"((r)[21]), "=r"((r)[22]), "=r"((r)[23]),        \
          "=r"((r)[24]), "=r"((r)[25]), "=r"((r)[26]), "=r"((r)[27]),        \
          "=r"((r)[28]), "=r"((r)[29]), "=r"((r)[30]), "=r"((r)[31])         \
        : "r"(addr))

__device__ __forceinline__ u32 sw128(u32 off) { return off ^ ((off >> 3) & 0x70); }
__device__ __forceinline__ u32 sw64(u32 off)  { return off ^ ((off >> 3) & 0x30); }

#define DESC_BASE   ((2ull << 61) | (1ull << 46) | (64ull << 32) | (1ull << 16))
#define DESC_BASE64 ((4ull << 61) | (1ull << 46) | (32ull << 32) | (1ull << 16))
__device__ __forceinline__ ull mk_desc(u32 addr)   { return DESC_BASE   | ((ull)(addr >> 4) & 0x3FFF); }
__device__ __forceinline__ ull mk_desc64(u32 addr) { return DESC_BASE64 | ((ull)(addr >> 4) & 0x3FFF); }

#define MMA_IDESC 0x8400490u   // F32 accum, BF16xBF16, M=128, N=256
#endif  // TCOK

// ---- k1 smem layout: hdr 1024 | staging x2 (50304 each) | opsets x2 (49152 each)
#define SM_TPTR 0
#define MB0 8
#define MB1 16
#define K1_STG_SZ 50304                    // smv 128 + K 32x132x4 + V 32x260x4
#define K1_OPS (1024 + 2 * K1_STG_SZ)      // 101632
#define K1_SET 49152                       // AH 8192 | AL 8192 | BH 16384 | BL 16384
#define K1_TOTAL (K1_OPS + 2 * K1_SET)     // 199936

// ---- k6 smem layout: hdr 1024 | opsets x2 (98304 each)
#define K6_SET 98304                       // AH 16384 | AL 16384 | BH 32768 | BL 32768
#define K6_TOTAL (1024 + 2 * K6_SET)       // 197632

// ---------------- mask detect + canonicalize (+cm) ----------------
__global__ void k_detect(const unsigned char* __restrict__ raw) {
    int idx = blockIdx.x * blockDim.x + threadIdx.x;   // < 16384
    if (raw[idx * 4 + 1] != 0) atomicOr(&g_kind, 1);
}

__global__ void k_maskconv(const void* __restrict__ rawv) {
    int n = blockIdx.x * blockDim.x + threadIdx.x;
    bool padded;
    if (g_kind) padded = ((const unsigned char*)rawv)[n] != 0;
    else        padded = ((const unsigned int*)rawv)[n] != 0u;
    float m = padded ? 0.f : 1.f;
    g_m[n] = m;
    float s = m;
#pragma unroll
    for (int o = 16; o > 0; o >>= 1) s += __shfl_xor_sync(0xffffffffu, s, o);
    __shared__ float red[8];
    int wid = threadIdx.x >> 5, lane = threadIdx.x & 31;
    if (lane == 0) red[wid] = s;
    __syncthreads();
    if (threadIdx.x == 0) {
        float t = 0.f;
        for (int i = 0; i < 8; i++) t += red[i];
        atomicAdd(&g_cm[n >> 13], t);
    }
}

__global__ void k_zero() {
    int i = blockIdx.x * blockDim.x + threadIdx.x;
    if (i < B_ * D_ * D_) g_S[i] = 0.f;
    if (i < B_ * D_) { g_rk[i] = 0.f; g_rv[i] = 0.f; }
    if (i < B_) g_cm[i] = 0.f;
    if (i == 0) g_kind = 0;
}

// ---------------- k1: S[b] += K_m^T V  (pipelined cp.async + tcgen05) --------
// grid (16 chunks, 2 slabs, B), 512 threads. 16 windows of n=32, K=32 SW64.
__global__ void __launch_bounds__(512, 1)
k1_mma(const float* __restrict__ key, const float* __restrict__ value) {
#if TCOK
    extern __shared__ char smem[];
    const u32 sb = smem_u32(smem);
    const int tid = threadIdx.x, wid = tid >> 5, lid = tid & 31;
    const int b = blockIdx.z, slab = blockIdx.y, chunk = blockIdx.x;
    const int d0 = slab * 128;
    const int n_start = chunk * 512;

    if (wid == 0) tmem_alloc(sb + SM_TPTR, 256);
    if (tid == 0) { mbar_init(sb + MB0, 1); mbar_init(sb + MB1, 1); }
    __syncthreads();
    u32 tbase;
    asm volatile("ld.shared.b32 %0, [%1];" : "=r"(tbase) : "r"(sb + SM_TPTR));

    const float* keyb = key + (size_t)b * N_ * D_ + d0;
    const float* valb = value + (size_t)b * N_ * D_;
    const float* mb_ = g_m + (size_t)b * N_;

    // stage window c into staging buffer s (pure cp.async, 7 per thread)
    auto stage_issue = [&](int c, int s) {
        const int n = n_start + c * 32;
        const u32 sbase = sb + 1024 + s * K1_STG_SZ;
        if (tid < 8) cp16(sbase + tid * 16, mb_ + n + tid * 4);
#pragma unroll
        for (int k = 0; k < 2; k++) {
            int i = tid + 512 * k, r = i >> 5, cc = i & 31;
            cp16(sbase + 128 + r * 528 + cc * 16, keyb + (size_t)(n + r) * D_ + cc * 4);
        }
#pragma unroll
        for (int k = 0; k < 4; k++) {
            int i = tid + 512 * k, r = i >> 6, cc = i & 63;
            cp16(sbase + 128 + 16896 + r * 1040 + cc * 16, valb + (size_t)(n + r) * D_ + cc * 4);
        }
    };

    float skacc = 0.f, svacc = 0.f;

    stage_issue(0, 0);
    cp_commit();

    for (int c = 0; c < 16; c++) {
        const int s = c & 1;
        if (c < 15) { stage_issue(c + 1, s ^ 1); cp_commit(); cp_wait<1>(); }
        else cp_wait<0>();
        __syncthreads();
        if (c >= 2) mbar_wait(sb + (s ? MB1 : MB0), ((c >> 1) - 1) & 1);

        const float* smv  = (const float*)(smem + 1024 + s * K1_STG_SZ);
        const float* stgK = smv + 32;
        const float* stgV = stgK + 32 * 132;
        const u32 ops = sb + K1_OPS + s * K1_SET;

        // A: 128 d-rows x 32 n (masked key, transposed) -> SW64
        {
            int r = tid & 127, g = tid >> 7;   // g 0..3
            uint4 hv, lv;
            float f0, f1;
            f0 = stgK[(g * 8 + 0) * 132 + r] * smv[g * 8 + 0];
            f1 = stgK[(g * 8 + 1) * 132 + r] * smv[g * 8 + 1];
            skacc += f0 + f1; cvt2(f0, f1, hv.x, lv.x);
            f0 = stgK[(g * 8 + 2) * 132 + r] * smv[g * 8 + 2];
            f1 = stgK[(g * 8 + 3) * 132 + r] * smv[g * 8 + 3];
            skacc += f0 + f1; cvt2(f0, f1, hv.y, lv.y);
            f0 = stgK[(g * 8 + 4) * 132 + r] * smv[g * 8 + 4];
            f1 = stgK[(g * 8 + 5) * 132 + r] * smv[g * 8 + 5];
            skacc += f0 + f1; cvt2(f0, f1, hv.z, lv.z);
            f0 = stgK[(g * 8 + 6) * 132 + r] * smv[g * 8 + 6];
            f1 = stgK[(g * 8 + 7) * 132 + r] * smv[g * 8 + 7];
            skacc += f0 + f1; cvt2(f0, f1, hv.w, lv.w);
            u32 sw = sw64((u32)(r * 64 + g * 16));
            *(uint4*)(smem + (ops - sb) + sw) = hv;
            *(uint4*)(smem + (ops - sb) + 8192 + sw) = lv;
        }
        // B: 256 e-rows x 32 n (raw value, transposed) -> SW64; masked sums
#pragma unroll
        for (int k = 0; k < 2; k++) {
            int i = tid + 512 * k;
            int r = i & 255, g = i >> 8;       // g 0..3
            uint4 hv, lv;
            float f0, f1;
            f0 = stgV[(g * 8 + 0) * 260 + r]; f1 = stgV[(g * 8 + 1) * 260 + r];
            svacc += smv[g * 8 + 0] * f0 + smv[g * 8 + 1] * f1; cvt2(f0, f1, hv.x, lv.x);
            f0 = stgV[(g * 8 + 2) * 260 + r]; f1 = stgV[(g * 8 + 3) * 260 + r];
            svacc += smv[g * 8 + 2] * f0 + smv[g * 8 + 3] * f1; cvt2(f0, f1, hv.y, lv.y);
            f0 = stgV[(g * 8 + 4) * 260 + r]; f1 = stgV[(g * 8 + 5) * 260 + r];
            svacc += smv[g * 8 + 4] * f0 + smv[g * 8 + 5] * f1; cvt2(f0, f1, hv.z, lv.z);
            f0 = stgV[(g * 8 + 6) * 260 + r]; f1 = stgV[(g * 8 + 7) * 260 + r];
            svacc += smv[g * 8 + 6] * f0 + smv[g * 8 + 7] * f1; cvt2(f0, f1, hv.w, lv.w);
            u32 sw = sw64((u32)(r * 64 + g * 16));
            *(uint4*)(smem + (ops - sb) + 16384 + sw) = hv;
            *(uint4*)(smem + (ops - sb) + 32768 + sw) = lv;
        }
        __syncthreads();
        fence_async_proxy();
        if (wid == 0 && elect1()) {
            const ull dAH = mk_desc64(ops), dAL = mk_desc64(ops + 8192);
            const ull dBH = mk_desc64(ops + 16384), dBL = mk_desc64(ops + 32768);
#pragma unroll
            for (int ks = 0; ks < 2; ks++) {
                ull o = (ull)(ks * 2);
                mma_f16_ss(tbase, dAH + o, dBH + o, MMA_IDESC, !(c == 0 && ks == 0));
                mma_f16_ss(tbase, dAH + o, dBL + o, MMA_IDESC, 1);
                mma_f16_ss(tbase, dAL + o, dBH + o, MMA_IDESC, 1);
            }
            mma_commit(sb + (s ? MB1 : MB0));
        }
    }
    mbar_wait(sb + MB0, 1);   // 8 commits each -> parity 1
    mbar_wait(sb + MB1, 1);
    tc_fence_after();

    if (wid < 4) {
        float* dst0 = g_S + ((size_t)b * D_ + d0 + wid * 32 + lid) * D_;
#pragma unroll
        for (int blk = 0; blk < 8; blk++) {
            u32 r[32];
            LDTM32(r, tbase + blk * 32);
            tmem_wait_ld();
#pragma unroll
            for (int cc = 0; cc < 32; cc++)
                atomicAdd(dst0 + blk * 32 + cc, __uint_as_float(r[cc]));
        }
    }
    __syncthreads();
    // side-sum reductions (staging area free now)
    float* sred = (float*)(smem + 1024);
    sred[tid] = skacc;
    sred[512 + tid] = svacc;
    __syncthreads();
    if (tid < 128) {   // A partials at {r, r+128, r+256, r+384}
        float s2 = sred[tid] + sred[tid + 128] + sred[tid + 256] + sred[tid + 384];
        atomicAdd(&g_rk[b * D_ + d0 + tid], s2);
    }
    if (slab == 0 && tid < 256) {   // B partials at {r, r+256}
        float s2 = sred[512 + tid] + sred[512 + tid + 256];
        atomicAdd(&g_rv[b * D_ + tid], s2);
    }
    __syncthreads();
    if (tid == 0) { mbar_inval(sb + MB0); mbar_inval(sb + MB1); }
    __syncthreads();
    if (wid == 0) tmem_dealloc(tbase, 256);
#else
    // FFMA fallback (non-'a' PTX stage only)
    const int tid = threadIdx.x;
    const int b = blockIdx.z, d0 = blockIdx.y * 128, chunk = blockIdx.x;
    const int n_start = chunk * 512;
    for (int idx = tid; idx < 128 * 256; idx += 512) {
        int d = d0 + (idx >> 8), e = idx & 255;
        float acc = 0.f;
        for (int n = n_start; n < n_start + 512; n++) {
            float m = g_m[(size_t)b * N_ + n];
            acc += m * key[((size_t)b * N_ + n) * D_ + d] * value[((size_t)b * N_ + n) * D_ + e];
        }
        atomicAdd(&g_S[((size_t)b * D_ + d) * D_ + e], acc);
    }
    if (tid < 128) {
        float s = 0.f;
        for (int n = n_start; n < n_start + 512; n++)
            s += g_m[(size_t)b * N_ + n] * key[((size_t)b * N_ + n) * D_ + d0 + tid];
        atomicAdd(&g_rk[b * D_ + d0 + tid], s);
    }
    if (blockIdx.y == 0 && tid < 256) {
        float s = 0.f;
        for (int n = n_start; n < n_start + 512; n++)
            s += g_m[(size_t)b * N_ + n] * value[((size_t)b * N_ + n) * D_ + tid];
        atomicAdd(&g_rv[b * D_ + tid], s);
    }
#endif
}

// ---------------- k_uw: u = Wk@rk, w = Wv@rv ----------------
__global__ void k_uw(const float* __restrict__ Wk, const float* __restrict__ Wv) {
    int b = blockIdx.x, d = threadIdx.x;
    float su = 0.f, sw = 0.f;
    for (int i = 0; i < D_; i++) {
        su += Wk[d * D_ + i] * g_rk[b * D_ + i];
        sw += Wv[d * D_ + i] * g_rv[b * D_ + i];
    }
    g_u[b * D_ + d] = su;
    g_w[b * D_ + d] = sw;
}

// ---------------- k2: T1 = Wk @ S ----------------
__global__ void __launch_bounds__(256, 1)
k2_T1(const float* __restrict__ Wk) {
    const int b = blockIdx.y, d0 = blockIdx.x * 16;
    const int tid = threadIdx.x, tx = tid & 15, ty = tid >> 4;
    __shared__ float sA[16][16];
    __shared__ float sB[16][256];
    ull acc[8];
#pragma unroll
    for (int p = 0; p < 8; p++) acc[p] = 0ull;
    const float* Sb = g_S + b * D_ * D_;
    for (int i0 = 0; i0 < D_; i0 += 16) {
        __syncthreads();
        if (tid < 64) {
            int r = tid >> 2, q = tid & 3;
            *(float4*)&sA[r][q * 4] = *(const float4*)(Wk + (size_t)(d0 + r) * D_ + i0 + q * 4);
        }
#pragma unroll
        for (int i = 0; i < 4; i++) {
            int idx = tid + 256 * i;
            int r = idx >> 6, q = idx & 63;
            *(float4*)&sB[r][q * 4] = *(const float4*)(Sb + (size_t)(i0 + r) * D_ + q * 4);
        }
        __syncthreads();
#pragma unroll
        for (int ii = 0; ii < 16; ii++) {
            float a = sA[ty][ii];
            ull a2 = pack2(a, a);
#pragma unroll
            for (int p = 0; p < 8; p++)
                acc[p] = ffma2(a2, *(const ull*)&sB[ii][2 * tx + 32 * p], acc[p]);
        }
    }
    float* T1b = g_T1 + b * D_ * D_;
    int row = d0 + ty;
#pragma unroll
    for (int p = 0; p < 8; p++) {
        float lo, hi; unpack2(acc[p], lo, hi);
        *(float2*)&T1b[row * D_ + 2 * tx + 32 * p] = make_float2(lo, hi);
    }
}

// ---------------- k3: A = (T1 @ Wv^T + rank-1) / sqrt(8) ----------------
__global__ void __launch_bounds__(256, 1)
k3_A(const float* __restrict__ Wv, const float* __restrict__ bk,
     const float* __restrict__ bv) {
    const int b = blockIdx.y, d0 = blockIdx.x * 16;
    const int tid = threadIdx.x, tx = tid & 15, ty = tid >> 4;
    __shared__ float sA[16][16];
    __shared__ float sB[16][258];
    ull acc[8];
#pragma unroll
    for (int p = 0; p < 8; p++) acc[p] = 0ull;
    const float* T1b = g_T1 + b * D_ * D_;
    for (int j0 = 0; j0 < D_; j0 += 16) {
        __syncthreads();
        if (tid < 64) {
            int r = tid >> 2, q = tid & 3;
            *(float4*)&sA[r][q * 4] = *(const float4*)(T1b + (size_t)(d0 + r) * D_ + j0 + q * 4);
        }
#pragma unroll
        for (int i = 0; i < 4; i++) {
            int idx = tid + 256 * i;
            int q = idx & 3, e = idx >> 2;
            float4 v = *(const float4*)(Wv + (size_t)e * D_ + j0 + q * 4);
            sB[q * 4 + 0][e] = v.x; sB[q * 4 + 1][e] = v.y;
            sB[q * 4 + 2][e] = v.z; sB[q * 4 + 3][e] = v.w;
        }
        __syncthreads();
#pragma unroll
        for (int jj = 0; jj < 16; jj++) {
            float a = sA[ty][jj];
            ull a2 = pack2(a, a);
#pragma unroll
            for (int p = 0; p < 8; p++)
                acc[p] = ffma2(a2, *(const ull*)&sB[jj][2 * tx + 32 * p], acc[p]);
        }
    }
    const int d = d0 + ty;
    const float u_d = g_u[b * D_ + d], bk_d = bk[d], cmv = g_cm[b];
    const float inv = 0.3535533905932738f;
    float* Ab = g_A + b * D_ * D_;
#pragma unroll
    for (int p = 0; p < 8; p++) {
        float lo, hi; unpack2(acc[p], lo, hi);
        int e = 2 * tx + 32 * p;
        float bv0 = bv[e], bv1 = bv[e + 1];
        float w0 = g_w[b * D_ + e], w1 = g_w[b * D_ + e + 1];
        lo = (lo + u_d * bv0 + bk_d * w0 + cmv * bk_d * bv0) * inv;
        hi = (hi + u_d * bv1 + bk_d * w1 + cmv * bk_d * bv1) * inv;
        *(float2*)&Ab[d * D_ + e] = make_float2(lo, hi);
    }
}

// ---------------- k4: column softmax + t = bq^T aw ----------------
__global__ void k4_softmax(const float* __restrict__ bq) {
    const int b = blockIdx.y;
    const int w = threadIdx.x >> 5, lane = threadIdx.x & 31;
    const int e = blockIdx.x * 8 + w;
    float* col = g_A + b * D_ * D_ + e;
    float v[8];
#pragma unroll
    for (int s = 0; s < 8; s++) v[s] = col[(lane + 32 * s) * D_];
    float mx = v[0];
#pragma unroll
    for (int s = 1; s < 8; s++) mx = fmaxf(mx, v[s]);
#pragma unroll
    for (int o = 16; o > 0; o >>= 1) mx = fmaxf(mx, __shfl_xor_sync(0xffffffffu, mx, o));
    float sum = 0.f;
#pragma unroll
    for (int s = 0; s < 8; s++) { v[s] = expf(v[s] - mx); sum += v[s]; }
#pragma unroll
    for (int o = 16; o > 0; o >>= 1) sum += __shfl_xor_sync(0xffffffffu, sum, o);
    const float isum = 1.f / sum;
    float tacc = 0.f;
#pragma unroll
    for (int s = 0; s < 8; s++) {
        float p = v[s] * isum;
        col[(lane + 32 * s) * D_] = p;
        tacc += p * bq[lane + 32 * s];
    }
#pragma unroll
    for (int o = 16; o > 0; o >>= 1) tacc += __shfl_xor_sync(0xffffffffu, tacc, o);
    if (lane == 0) g_t[b * D_ + e] = tacc;
}

// ---------------- k5: M^T[e][i] = sum_d Wq[d][i] aw[d][e] -> bf16 hi/lo ------
__global__ void __launch_bounds__(256, 1)
k5_M(const float* __restrict__ Wq) {
    const int b = blockIdx.y, i0 = blockIdx.x * 16;
    const int tid = threadIdx.x, tx = tid & 15, ty = tid >> 4;
    __shared__ float sA[16][17];
    __shared__ float sB[16][256];
    ull acc[8];
#pragma unroll
    for (int p = 0; p < 8; p++) acc[p] = 0ull;
    const float* awb = g_A + b * D_ * D_;
    for (int dd0 = 0; dd0 < D_; dd0 += 16) {
        __syncthreads();
        if (tid < 64) {
            int r = tid >> 2, q = tid & 3;
            float4 v = *(const float4*)(Wq + (size_t)(dd0 + r) * D_ + i0 + q * 4);
            sA[q * 4 + 0][r] = v.x; sA[q * 4 + 1][r] = v.y;
            sA[q * 4 + 2][r] = v.z; sA[q * 4 + 3][r] = v.w;
        }
#pragma unroll
        for (int i = 0; i < 4; i++) {
            int idx = tid + 256 * i;
            int r = idx >> 6, q = idx & 63;
            *(float4*)&sB[r][q * 4] = *(const float4*)(awb + (size_t)(dd0 + r) * D_ + q * 4);
        }
        __syncthreads();
#pragma unroll
        for (int dd = 0; dd < 16; dd++) {
            float a = sA[ty][dd];
            ull a2 = pack2(a, a);
#pragma unroll
            for (int p = 0; p < 8; p++)
                acc[p] = ffma2(a2, *(const ull*)&sB[dd][2 * tx + 32 * p], acc[p]);
        }
    }
    const int row = i0 + ty;
#pragma unroll
    for (int p = 0; p < 8; p++) {
        float lo, hi; unpack2(acc[p], lo, hi);
        int e0 = 2 * tx + 32 * p, e1 = e0 + 1;
        __nv_bfloat16 h0 = __float2bfloat16(lo);
        __nv_bfloat16 h1 = __float2bfloat16(hi);
        g_MTH[((size_t)b * D_ + e0) * D_ + row] = h0;
        g_MTL[((size_t)b * D_ + e0) * D_ + row] = __float2bfloat16(lo - __bfloat162float(h0));
        g_MTH[((size_t)b * D_ + e1) * D_ + row] = h1;
        g_MTL[((size_t)b * D_ + e1) * D_ + row] = __float2bfloat16(hi - __bfloat162float(h1));
    }
}

// ---------------- k6: out = query @ M + t  (pipelined, double-buffered) ------
__global__ void __launch_bounds__(512, 1)
k6_mma(const float* __restrict__ query, float* __restrict__ out) {
#if TCOK
    extern __shared__ char smem[];
    const u32 sb = smem_u32(smem);
    const int tid = threadIdx.x, wid = tid >> 5, lid = tid & 31;
    const int b = blockIdx.y, n0 = blockIdx.x * 128;

    if (wid == 0) tmem_alloc(sb + SM_TPTR, 256);
    if (tid == 0) { mbar_init(sb + MB0, 1); mbar_init(sb + MB1, 1); }
    __syncthreads();
    u32 tbase;
    asm volatile("ld.shared.b32 %0, [%1];" : "=r"(tbase) : "r"(sb + SM_TPTR));

    const float* qb = query + ((size_t)b * N_ + n0) * D_;
    const size_t bbase0 = (size_t)b * D_ * D_;

    for (int c = 0; c < 4; c++) {
        const int s = c & 1;
        const int dc = c * 64;
        const u32 ops = sb + 1024 + s * K6_SET;
        // issue q LDGs into regs early (overlap mbar wait + B copies)
        float4 qa0, qa1, qb0, qb1;
        int r0 = tid >> 3, c160 = tid & 7;
        int r1 = (tid + 512) >> 3, c161 = tid & 7;
        {
            const float* src0 = qb + (size_t)r0 * D_ + dc + c160 * 8;
            const float* src1 = qb + (size_t)r1 * D_ + dc + c161 * 8;
            qa0 = *(const float4*)(src0); qa1 = *(const float4*)(src0 + 4);
            qb0 = *(const float4*)(src1); qb1 = *(const float4*)(src1 + 4);
        }
        if (c >= 2) mbar_wait(sb + (s ? MB1 : MB0), 0);
        // B: cp.async straight into swizzled operand buffers (L2-resident)
#pragma unroll
        for (int k = 0; k < 4; k++) {
            int i = tid + 512 * k;
            int r = i >> 3, c16 = i & 7;
            size_t off = bbase0 + (size_t)r * D_ + dc + c16 * 8;
            u32 sw = sw128((u32)(r * 128 + c16 * 16));
            cp16(ops + 32768 + sw, g_MTH + off);
            cp16(ops + 65536 + sw, g_MTL + off);
        }
        cp_commit();
        // A: convert q regs -> SW128
        {
            uint4 hv, lv;
            cvt2(qa0.x, qa0.y, hv.x, lv.x);
            cvt2(qa0.z, qa0.w, hv.y, lv.y);
            cvt2(qa1.x, qa1.y, hv.z, lv.z);
            cvt2(qa1.z, qa1.w, hv.w, lv.w);
            u32 sw = sw128((u32)(r0 * 128 + c160 * 16));
            *(uint4*)(smem + (ops - sb) + sw) = hv;
            *(uint4*)(smem + (ops - sb) + 16384 + sw) = lv;
            cvt2(qb0.x, qb0.y, hv.x, lv.x);
            cvt2(qb0.z, qb0.w, hv.y, lv.y);
            cvt2(qb1.x, qb1.y, hv.z, lv.z);
            cvt2(qb1.z, qb1.w, hv.w, lv.w);
            sw = sw128((u32)(r1 * 128 + c161 * 16));
            *(uint4*)(smem + (ops - sb) + sw) = hv;
            *(uint4*)(smem + (ops - sb) + 16384 + sw) = lv;
        }
        cp_wait<0>();
        __syncthreads();
        fence_async_proxy();
        if (wid == 0 && elect1()) {
            const ull dAH = mk_desc(ops), dAL = mk_desc(ops + 16384);
            const ull dBH = mk_desc(ops + 32768), dBL = mk_desc(ops + 65536);
#pragma unroll
            for (int ks = 0; ks < 4; ks++) {
                ull o = (ull)(ks * 2);
                mma_f16_ss(tbase, dAH + o, dBH + o, MMA_IDESC, !(c == 0 && ks == 0));
                mma_f16_ss(tbase, dAH + o, dBL + o, MMA_IDESC, 1);
                mma_f16_ss(tbase, dAL + o, dBH + o, MMA_IDESC, 1);
            }
            mma_commit(sb + (s ? MB1 : MB0));
        }
    }
    mbar_wait(sb + MB0, 1);   // 2 commits each -> parity 1
    mbar_wait(sb + MB1, 1);
    tc_fence_after();

    float* stage = (float*)(smem + 1024);   // reuse opset 0 (MMAs all done)
    for (int cb = 0; cb < 4; cb++) {
        __syncthreads();
        if (wid < 4) {
            u32 r0a[32], r1a[32];
            LDTM32(r0a, tbase + cb * 64);
            LDTM32(r1a, tbase + cb * 64 + 32);
            tmem_wait_ld();
            float* srow = stage + (wid * 32 + lid) * 68;
#pragma unroll
            for (int cc = 0; cc < 32; cc++) {
                srow[cc] = __uint_as_float(r0a[cc]);
                srow[32 + cc] = __uint_as_float(r1a[cc]);
            }
        }
        __syncthreads();
#pragma unroll
        for (int i = tid; i < 2048; i += 512) {
            int r = i >> 4, c4 = i & 15;
            float4 v = *(float4*)(stage + r * 68 + c4 * 4);
            int e = cb * 64 + c4 * 4;
            v.x += g_t[b * D_ + e];
            v.y += g_t[b * D_ + e + 1];
            v.z += g_t[b * D_ + e + 2];
            v.w += g_t[b * D_ + e + 3];
            *(float4*)(out + ((size_t)b * N_ + n0 + r) * D_ + e) = v;
        }
    }
    __syncthreads();
    if (tid == 0) { mbar_inval(sb + MB0); mbar_inval(sb + MB1); }
    __syncthreads();
    if (wid == 0) tmem_dealloc(tbase, 256);
#else
    // FFMA fallback
    const int tid = threadIdx.x;
    const int b = blockIdx.y, n0 = blockIdx.x * 128;
    for (int idx = tid; idx < 128 * 256; idx += 512) {
        int n = n0 + (idx >> 8), e = idx & 255;
        const float* q = query + ((size_t)b * N_ + n) * D_;
        const __nv_bfloat16* mh = g_MTH + ((size_t)b * D_ + e) * D_;
        const __nv_bfloat16* ml = g_MTL + ((size_t)b * D_ + e) * D_;
        float acc = g_t[b * D_ + e];
        for (int d = 0; d < D_; d++)
            acc += q[d] * (__bfloat162float(mh[d]) + __bfloat162float(ml[d]));
        out[((size_t)b * N_ + n) * D_ + e] = acc;
    }
#endif
}

// ---------------- launch ----------------
extern "C" void kernel_launch(void* const* d_in, const int* in_sizes, int n_in,
                              void* d_out, int out_size) {
    const float* query = (const float*)d_in[0];
    const float* key   = (const float*)d_in[1];
    const float* value = (const float*)d_in[2];
    const void*  maskraw = d_in[3];
    int o = (n_in >= 11) ? 5 : 4;
    const float* Wq = (const float*)d_in[o + 0];
    const float* bq = (const float*)d_in[o + 1];
    const float* Wk = (const float*)d_in[o + 2];
    const float* bk = (const float*)d_in[o + 3];
    const float* Wv = (const float*)d_in[o + 4];
    const float* bv = (const float*)d_in[o + 5];
    float* out = (float*)d_out;
    (void)in_sizes; (void)out_size;

    cudaFuncSetAttribute(k1_mma, cudaFuncAttributeMaxDynamicSharedMemorySize, K1_TOTAL);
    cudaFuncSetAttribute(k6_mma, cudaFuncAttributeMaxDynamicSharedMemorySize, K6_TOTAL);

    k_zero<<<(B_ * D_ * D_ + 255) / 256, 256>>>();
    k_detect<<<64, 256>>>((const unsigned char*)maskraw);
    k_maskconv<<<(B_ * N_) / 256, 256>>>(maskraw);
    k1_mma<<<dim3(16, 2, B_), 512, K1_TOTAL>>>(key, value);
    k_uw<<<B_, 256>>>(Wk, Wv);
    k2_T1<<<dim3(16, B_), 256>>>(Wk);
    k3_A<<<dim3(16, B_), 256>>>(Wv, bk, bv);
    k4_softmax<<<dim3(32, B_), 256>>>(bq);
    k5_M<<<dim3(16, B_), 256>>>(Wq);
    k6_mma<<<dim3(64, B_), 512, K6_TOTAL>>>(query, out);
}